// round 15
// baseline (speedup 1.0000x reference)
#include <cuda_runtime.h>
#include <cuda_fp16.h>
#include <cstdint>
#include <math.h>

// AttentionBlock, rank-7 factored form (round 15).
// t = (x·Wqk)·y^T where Wqk = Wq·Wk^T·(log2e/16)  -> MMA outputs log2-domain scores.
// E = 2^t via ex2.approx.f16x2, Rv = relu(t) via max.f16x2.
// accEy = E·[y|1], accRy = Rv·[y|1]  (col 7 = Z / Rsum').
// out = ((accEy/Z + 0.1·ln2·accRy)/(0.1·ln2·Rsum'+1)) · Wv.
// Round 15: epi_kernel DELETED — fused into attn via last-CTA-per-qblk
// reduction (threadfence + atomic counter; fixed-order split sum = deterministic).

#define N_Q   16384
#define MCTX  4096
#define S_IN  256
#define D_P   256
#define KSPLIT 8
#define KEYS_PER (MCTX / KSPLIT)   // 512
#define TILES (KEYS_PER / 32)      // 16
#define GTILES (MCTX / 32)         // 128
#define NQB   (N_Q / 128)          // 128 query blocks

// scratch
__device__ float    g_Wqk[S_IN * 8];             // Wq@Wk^T * log2e/16, [256][8] (col7=0)
__device__ uint2    g_QKf [(N_Q / 16) * 32];     // QKp A-frags (k8): [qgroup][lane]
__device__ uint32_t g_ySf [GTILES * 128];        // y^T B-frags (k8,S):  [tile][lane][nt4]
__device__ uint32_t g_yPf [GTILES * 128];        // y B-frags (k16,PV): [tile][lane][ks2][r2]
__device__ float    g_pE  [KSPLIT * N_Q * 8];    // partial accEy (col7 = Z)
__device__ float    g_pR  [KSPLIT * N_Q * 8];    // partial accRy (col7 = Rsum')
__device__ unsigned g_cnt [NQB];                 // per-qblk arrival counters

#define SCALE_L2E 0.09016844129899994f   /* log2e / 16 */
#define C01LN2    0.06931471805599453f   /* 0.1 * ln2 */

// ---------------------------------------------------------------- helpers
__device__ __forceinline__ uint32_t smem_u32(const void* p) {
    uint32_t a;
    asm("{ .reg .u64 t; cvta.to.shared.u64 t, %1; cvt.u32.u64 %0, t; }" : "=r"(a) : "l"(p));
    return a;
}
__device__ __forceinline__ uint32_t packh2(float lo, float hi) {
    __half2 h = __floats2half2_rn(lo, hi);
    return *(uint32_t*)&h;
}
__device__ __forceinline__ uint32_t h2ex2(uint32_t t) {
    uint32_t e;
    asm("ex2.approx.f16x2 %0, %1;" : "=r"(e) : "r"(t));
    return e;
}
__device__ __forceinline__ uint32_t h2relu(uint32_t t) {
    uint32_t r;
    asm("max.f16x2 %0, %1, %2;" : "=r"(r) : "r"(t), "r"(0u));
    return r;
}
__device__ __forceinline__ void lds128(uint32_t r[4], uint32_t a) {
    asm volatile("ld.shared.v4.b32 {%0,%1,%2,%3}, [%4];"
        : "=r"(r[0]), "=r"(r[1]), "=r"(r[2]), "=r"(r[3]) : "r"(a));
}
__device__ __forceinline__ void mma_f16_k8(float c[4], const uint32_t a[2], uint32_t b) {
    asm volatile("mma.sync.aligned.m16n8k8.row.col.f32.f16.f16.f32 "
        "{%0,%1,%2,%3}, {%4,%5}, {%6}, {%0,%1,%2,%3};"
        : "+f"(c[0]), "+f"(c[1]), "+f"(c[2]), "+f"(c[3])
        : "r"(a[0]), "r"(a[1]), "r"(b));
}
__device__ __forceinline__ void mma_f16(float c[4], const uint32_t a[4],
                                        uint32_t b0, uint32_t b1) {
    asm volatile("mma.sync.aligned.m16n8k16.row.col.f32.f16.f16.f32 "
        "{%0,%1,%2,%3}, {%4,%5,%6,%7}, {%8,%9}, {%0,%1,%2,%3};"
        : "+f"(c[0]), "+f"(c[1]), "+f"(c[2]), "+f"(c[3])
        : "r"(a[0]), "r"(a[1]), "r"(a[2]), "r"(a[3]), "r"(b0), "r"(b1));
}
#define CP16(dst, src) \
    asm volatile("cp.async.cg.shared.global [%0], [%1], 16;" :: "r"(dst), "l"(src))
#define CP_COMMIT() asm volatile("cp.async.commit_group;" ::: "memory")
#define CP_WAIT0()  asm volatile("cp.async.wait_group 0;" ::: "memory")

// ---------------------------------------------------------------- prep:
// blocks [0,32): Wqk (warp-per-row). Block 0 also zeroes arrival counters.
// blocks [32,160): y frag pack.
__global__ __launch_bounds__(256) void prep_kernel(const float* __restrict__ y,
                                                   const float* __restrict__ Wq,
                                                   const float* __restrict__ Wk) {
    int b = blockIdx.x;
    if (b < 32) {
        __shared__ float wks[7 * 256];
        int t = threadIdx.x;
        if (b == 0 && t < NQB) g_cnt[t] = 0;     // reset counters every launch
        for (int i = t; i < 7 * 256; i += 256) wks[i] = Wk[i];
        __syncthreads();
        int w = t >> 5, lane = t & 31;
        int row = b * 8 + w;
        float acc[7] = {};
        #pragma unroll
        for (int i = 0; i < 8; i++) {
            int p = i * 32 + lane;
            float v = Wq[row * 256 + p];
            #pragma unroll
            for (int j = 0; j < 7; j++) acc[j] = fmaf(v, wks[j * 256 + p], acc[j]);
        }
        #pragma unroll
        for (int j = 0; j < 7; j++) {
            #pragma unroll
            for (int off = 16; off > 0; off >>= 1)
                acc[j] += __shfl_xor_sync(0xffffffffu, acc[j], off);
        }
        if (lane == 0) {
            #pragma unroll
            for (int j = 0; j < 7; j++) g_Wqk[row * 8 + j] = acc[j] * SCALE_L2E;
            g_Wqk[row * 8 + 7] = 0.f;
        }
    } else {
        int u = (b - 32) * 256 + threadIdx.x;    // [0, 32768)
        if (u < 16384) {
            // S B-frag (k8), layout [tile][lane][nt]: key n = tile*32 + nt*8 + g
            int nt = u & 3, lane = (u >> 2) & 31, tile = u >> 7;
            int g = lane >> 2, q = lane & 3;
            int n = tile * 32 + nt * 8 + g;
            float v0 = (2 * q     < 7) ? y[n * 7 + 2 * q]     : 0.f;
            float v1 = (2 * q + 1 < 7) ? y[n * 7 + 2 * q + 1] : 0.f;   // k-dim pad = 0
            g_ySf[u] = packh2(v0, v1);
        } else {
            // PV B-frag (k16), layout [tile][lane][ks][r]: col 7 = 1.0 (Z/Rsum)
            int u2 = u - 16384;
            int r = u2 & 1, ks = (u2 >> 1) & 1, lane = (u2 >> 2) & 31, tile = u2 >> 7;
            int g = lane >> 2, q = lane & 3;
            int k0 = tile * 32 + ks * 16 + r * 8 + 2 * q;
            float v0 = (g < 7) ? y[(size_t)k0 * 7 + g]       : 1.0f;
            float v1 = (g < 7) ? y[(size_t)(k0 + 1) * 7 + g] : 1.0f;
            g_yPf[u2] = packh2(v0, v1);
        }
    }
}

// ---------------------------------------------------------------- QKp = x@Wqk -> A-frags
__global__ __launch_bounds__(256) void qkp_kernel(const float* __restrict__ x) {
    __shared__ float wqs[2048];
    int t = threadIdx.x;
    for (int i = t; i < 2048; i += 256) wqs[i] = g_Wqk[i];
    __syncthreads();
    int u = blockIdx.x * 256 + t;       // 32768 threads
    int lane = u & 31, qg = u >> 5;
    int g = lane >> 2, q = lane & 3;
    int r0 = qg * 16 + g, r1 = r0 + 8;
    int c0 = 2 * q, c1 = c0 + 1;
    float a00 = 0, a01 = 0, a10 = 0, a11 = 0;
    const float4* x0 = (const float4*)(x + (size_t)r0 * 256);
    const float4* x1 = (const float4*)(x + (size_t)r1 * 256);
    #pragma unroll 4
    for (int k4 = 0; k4 < 64; k4++) {
        float4 v0 = x0[k4], v1 = x1[k4];
        const float* ww = &wqs[k4 * 32];
        a00 = fmaf(v0.x, ww[c0], a00);       a01 = fmaf(v0.x, ww[c1], a01);
        a10 = fmaf(v1.x, ww[c0], a10);       a11 = fmaf(v1.x, ww[c1], a11);
        a00 = fmaf(v0.y, ww[8 + c0], a00);   a01 = fmaf(v0.y, ww[8 + c1], a01);
        a10 = fmaf(v1.y, ww[8 + c0], a10);   a11 = fmaf(v1.y, ww[8 + c1], a11);
        a00 = fmaf(v0.z, ww[16 + c0], a00);  a01 = fmaf(v0.z, ww[16 + c1], a01);
        a10 = fmaf(v1.z, ww[16 + c0], a10);  a11 = fmaf(v1.z, ww[16 + c1], a11);
        a00 = fmaf(v0.w, ww[24 + c0], a00);  a01 = fmaf(v0.w, ww[24 + c1], a01);
        a10 = fmaf(v1.w, ww[24 + c0], a10);  a11 = fmaf(v1.w, ww[24 + c1], a11);
    }
    uint2 o;
    o.x = packh2(a00, a01);
    o.y = packh2(a10, a11);
    g_QKf[u] = o;
}

// ---------------------------------------------------------------- fused attention + epilogue
// CTA: 256 threads, 128 queries, keys [split*512, +512). smem: 8K + 8K.
// Last CTA per qblk (atomic counter) reduces the 8 split partials in fixed
// index order and writes out = c @ Wv.
#define ATT_SMEM 16384

__global__ __launch_bounds__(256, 4) void attn_kernel(const float* __restrict__ Wv,
                                                      float* __restrict__ out) {
    extern __shared__ char smem[];
    const uint32_t sb = smem_u32(smem);
    const uint32_t SY = sb, PVS = sb + 8192;
    float (*c_s)[8] = (float(*)[8])smem;     // reused after main loop (4 KB)
    __shared__ bool isLast;

    const int t = threadIdx.x, w = t >> 5, lane = t & 31;
    const int g = lane >> 2, q = lane & 3;
    const int qblk = blockIdx.x, split = blockIdx.y;

    // load this split's y-fragments (once)
    {
        const uint32_t* ysrc = g_ySf + split * (TILES * 128);
        const uint32_t* psrc = g_yPf + split * (TILES * 128);
        #pragma unroll
        for (int i = 0; i < 2; i++) { int f = t + (i << 8); CP16(SY  + f * 16, ysrc + f * 4); }
        #pragma unroll
        for (int i = 0; i < 2; i++) { int f = t + (i << 8); CP16(PVS + f * 16, psrc + f * 4); }
        CP_COMMIT(); CP_WAIT0();
    }
    __syncthreads();

    uint2 qa = g_QKf[(qblk * 8 + w) * 32 + lane];
    uint32_t a8[2] = { qa.x, qa.y };

    float accE[4] = {}, accR[4] = {};

    #pragma unroll 2
    for (int tile = 0; tile < TILES; tile++) {
        // ---- scores (log2 domain): 16q x 32keys, 4 k8-HMMA, one lds128 ----
        float sc[4][4] = {};
        uint32_t bS[4];
        lds128(bS, SY + (uint32_t)(tile * 128 + lane * 4) * 4);
        mma_f16_k8(sc[0], a8, bS[0]);
        mma_f16_k8(sc[1], a8, bS[1]);
        mma_f16_k8(sc[2], a8, bS[2]);
        mma_f16_k8(sc[3], a8, bS[3]);

        // ---- convert in half2: pack t, E = ex2.f16x2, Rv = max.f16x2 ----
        uint32_t eh[4][2], rh[4][2];
        #pragma unroll
        for (int nt = 0; nt < 4; nt++) {
            uint32_t t01 = packh2(sc[nt][0], sc[nt][1]);
            uint32_t t23 = packh2(sc[nt][2], sc[nt][3]);
            eh[nt][0] = h2ex2(t01);   eh[nt][1] = h2ex2(t23);
            rh[nt][0] = h2relu(t01);  rh[nt][1] = h2relu(t23);
        }

        // ---- PV: accEy += E@[y|1], accRy += R@[y|1]; one lds128, 4 k16-HMMA ----
        uint32_t bP[4];
        lds128(bP, PVS + (uint32_t)(tile * 128 + lane * 4) * 4);
        {
            uint32_t aE0[4] = { eh[0][0], eh[0][1], eh[1][0], eh[1][1] };
            uint32_t aR0[4] = { rh[0][0], rh[0][1], rh[1][0], rh[1][1] };
            mma_f16(accE, aE0, bP[0], bP[1]);
            mma_f16(accR, aR0, bP[0], bP[1]);
        }
        {
            uint32_t aE1[4] = { eh[2][0], eh[2][1], eh[3][0], eh[3][1] };
            uint32_t aR1[4] = { rh[2][0], rh[2][1], rh[3][0], rh[3][1] };
            mma_f16(accE, aE1, bP[2], bP[3]);
            mma_f16(accR, aR1, bP[2], bP[3]);
        }
    }

    // store partials (col 7 carries Z / Rsum')
    const int qrow = qblk * 128 + w * 16 + g;
    const size_t b8 = (size_t)split * (N_Q * 8);
    *(float2*)&g_pE[b8 + (size_t)qrow * 8 + 2 * q]       = make_float2(accE[0], accE[1]);
    *(float2*)&g_pE[b8 + (size_t)(qrow + 8) * 8 + 2 * q] = make_float2(accE[2], accE[3]);
    *(float2*)&g_pR[b8 + (size_t)qrow * 8 + 2 * q]       = make_float2(accR[0], accR[1]);
    *(float2*)&g_pR[b8 + (size_t)(qrow + 8) * 8 + 2 * q] = make_float2(accR[2], accR[3]);

    // ---- last-CTA-per-qblk epilogue ----
    __threadfence();                 // make partials visible device-wide
    __syncthreads();                 // all warps' stores issued before arrival
    if (t == 0)
        isLast = (atomicAdd(&g_cnt[qblk], 1u) == KSPLIT - 1);
    __syncthreads();
    if (!isLast) return;

    // hoisted Wv column loads (overlap phase-1 latency)
    const int j = t & 63;
    float4 wv4[7];
    #pragma unroll
    for (int d = 0; d < 7; d++)
        wv4[d] = ((const float4*)(Wv + (size_t)d * 256))[j];

    // phase 1: 2 threads per row; thread (row = t>>1, hs = t&1) sums splits
    // 4*hs..4*hs+3 (fixed order), then xor-1 shuffle combine; hs==0 writes c_s.
    {
        const int row = t >> 1, hs = t & 1;
        const int qr = qblk * 128 + row;
        float ea[8] = {}, ra[8] = {};
        #pragma unroll
        for (int i = 0; i < 4; i++) {
            int s = hs * 4 + i;
            const float* pe = &g_pE[(size_t)s * (N_Q * 8) + (size_t)qr * 8];
            const float* pr = &g_pR[(size_t)s * (N_Q * 8) + (size_t)qr * 8];
            float4 e0 = *(const float4*)pe, e1 = *(const float4*)(pe + 4);
            float4 r0 = *(const float4*)pr, r1 = *(const float4*)(pr + 4);
            ea[0] += e0.x; ea[1] += e0.y; ea[2] += e0.z; ea[3] += e0.w;
            ea[4] += e1.x; ea[5] += e1.y; ea[6] += e1.z; ea[7] += e1.w;
            ra[0] += r0.x; ra[1] += r0.y; ra[2] += r0.z; ra[3] += r0.w;
            ra[4] += r1.x; ra[5] += r1.y; ra[6] += r1.z; ra[7] += r1.w;
        }
        #pragma unroll
        for (int jj = 0; jj < 8; jj++) {
            ea[jj] += __shfl_xor_sync(0xffffffffu, ea[jj], 1);
            ra[jj] += __shfl_xor_sync(0xffffffffu, ra[jj], 1);
        }
        if (hs == 0) {
            float iz = 1.f / ea[7];
            float dn = 1.f / fmaf(C01LN2, ra[7], 1.f);
            #pragma unroll
            for (int d = 0; d < 7; d++)
                c_s[row][d] = fmaf(ea[d], iz, C01LN2 * ra[d]) * dn;
            c_s[row][7] = 0.f;
        }
    }
    __syncthreads();

    // phase 2: thread t -> float4-col j, rows rg*32..+32 (rg = t>>6)
    const int rg = t >> 6;
    float* outb = out + (size_t)qblk * 128 * 256;
    #pragma unroll 4
    for (int r = 0; r < 32; r++) {
        int row = rg * 32 + r;
        const float* c = c_s[row];
        float4 o;
        o.x = c[0] * wv4[0].x; o.y = c[0] * wv4[0].y;
        o.z = c[0] * wv4[0].z; o.w = c[0] * wv4[0].w;
        #pragma unroll
        for (int d = 1; d < 7; d++) {
            o.x = fmaf(c[d], wv4[d].x, o.x);
            o.y = fmaf(c[d], wv4[d].y, o.y);
            o.z = fmaf(c[d], wv4[d].z, o.z);
            o.w = fmaf(c[d], wv4[d].w, o.w);
        }
        ((float4*)(outb + (size_t)row * 256))[j] = o;
    }
}

// ---------------------------------------------------------------------------
extern "C" void kernel_launch(void* const* d_in, const int* in_sizes, int n_in,
                              void* d_out, int out_size) {
    const float* x  = (const float*)d_in[0];
    const float* y  = (const float*)d_in[1];
    const float* Wq = (const float*)d_in[2];
    const float* Wk = (const float*)d_in[3];
    const float* Wv = (const float*)d_in[4];
    float* out = (float*)d_out;

    cudaFuncSetAttribute(attn_kernel, cudaFuncAttributeMaxDynamicSharedMemorySize,
                         ATT_SMEM);

    prep_kernel<<<160, 256>>>(y, Wq, Wk);
    qkp_kernel <<<128, 256>>>(x);
    attn_kernel<<<dim3(NQB, KSPLIT), 256, ATT_SMEM>>>(Wv, out);
}

// round 17
// speedup vs baseline: 1.0504x; 1.0504x over previous
#include <cuda_runtime.h>
#include <cuda_fp16.h>
#include <cstdint>
#include <math.h>

// AttentionBlock, rank-7 factored form (round 17).
// t = (x·Wqk)·y^T where Wqk = Wq·Wk^T·(log2e/16)  -> MMA outputs log2-domain scores.
// E = 2^t via ex2.approx.f16x2, Rv = relu(t) via max.f16x2.
// accEy = E·[y|1], accRy = Rv·[y|1]  (col 7 = Z / Rsum').
// out = ((accEy/Z + 0.1·ln2·accRy)/(0.1·ln2·Rsum'+1)) · Wv.
// Round 17: round-16 combo fusion with the OOB fixed — phase A1 uses the
// round-13 split (u<16384 -> S frag, else PV frag). attn/epi = round-13 exact.

#define N_Q   16384
#define MCTX  4096
#define S_IN  256
#define D_P   256
#define KSPLIT 8
#define KEYS_PER (MCTX / KSPLIT)   // 512
#define TILES (KEYS_PER / 32)      // 16
#define GTILES (MCTX / 32)         // 128

// scratch
__device__ float    g_Wqk[S_IN * 8];             // Wq@Wk^T * log2e/16, [256][8] (col7=0)
__device__ uint2    g_QKf [(N_Q / 16) * 32];     // QKp A-frags (k8): [qgroup][lane]
__device__ uint32_t g_ySf [GTILES * 128];        // y^T B-frags (k8,S):  [tile][lane][nt4]
__device__ uint32_t g_yPf [GTILES * 128];        // y B-frags (k16,PV): [tile][lane][ks2][r2]
__device__ float    g_pE  [KSPLIT * N_Q * 8];    // partial accEy (col7 = Z)
__device__ float    g_pR  [KSPLIT * N_Q * 8];    // partial accRy (col7 = Rsum')
__device__ unsigned g_bar;                       // barrier arrivals (reset in-kernel)
__device__ unsigned g_gate;                      // barrier generation (monotonic)

#define SCALE_L2E 0.09016844129899994f   /* log2e / 16 */
#define C01LN2    0.06931471805599453f   /* 0.1 * ln2 */

// ---------------------------------------------------------------- helpers
__device__ __forceinline__ uint32_t smem_u32(const void* p) {
    uint32_t a;
    asm("{ .reg .u64 t; cvta.to.shared.u64 t, %1; cvt.u32.u64 %0, t; }" : "=r"(a) : "l"(p));
    return a;
}
__device__ __forceinline__ uint32_t packh2(float lo, float hi) {
    __half2 h = __floats2half2_rn(lo, hi);
    return *(uint32_t*)&h;
}
__device__ __forceinline__ uint32_t h2ex2(uint32_t t) {
    uint32_t e;
    asm("ex2.approx.f16x2 %0, %1;" : "=r"(e) : "r"(t));
    return e;
}
__device__ __forceinline__ uint32_t h2relu(uint32_t t) {
    uint32_t r;
    asm("max.f16x2 %0, %1, %2;" : "=r"(r) : "r"(t), "r"(0u));
    return r;
}
__device__ __forceinline__ void lds128(uint32_t r[4], uint32_t a) {
    asm volatile("ld.shared.v4.b32 {%0,%1,%2,%3}, [%4];"
        : "=r"(r[0]), "=r"(r[1]), "=r"(r[2]), "=r"(r[3]) : "r"(a));
}
__device__ __forceinline__ void mma_f16_k8(float c[4], const uint32_t a[2], uint32_t b) {
    asm volatile("mma.sync.aligned.m16n8k8.row.col.f32.f16.f16.f32 "
        "{%0,%1,%2,%3}, {%4,%5}, {%6}, {%0,%1,%2,%3};"
        : "+f"(c[0]), "+f"(c[1]), "+f"(c[2]), "+f"(c[3])
        : "r"(a[0]), "r"(a[1]), "r"(b));
}
__device__ __forceinline__ void mma_f16(float c[4], const uint32_t a[4],
                                        uint32_t b0, uint32_t b1) {
    asm volatile("mma.sync.aligned.m16n8k16.row.col.f32.f16.f16.f32 "
        "{%0,%1,%2,%3}, {%4,%5,%6,%7}, {%8,%9}, {%0,%1,%2,%3};"
        : "+f"(c[0]), "+f"(c[1]), "+f"(c[2]), "+f"(c[3])
        : "r"(a[0]), "r"(a[1]), "r"(a[2]), "r"(a[3]), "r"(b0), "r"(b1));
}
#define CP16(dst, src) \
    asm volatile("cp.async.cg.shared.global [%0], [%1], 16;" :: "r"(dst), "l"(src))
#define CP_COMMIT() asm volatile("cp.async.commit_group;" ::: "memory")
#define CP_WAIT0()  asm volatile("cp.async.wait_group 0;" ::: "memory")

// ---------------------------------------------------------------- combo:
// grid 128 (ALL CTAs resident on 148 SMs -> spin barrier safe).
// Phase A: y frag packing, ONE item per thread, u = b*256+t in [0,32768):
//          u < 16384 -> S B-frag (g_ySf[u]); else PV B-frag (g_yPf[u-16384]).
//          Warps 0-1 additionally compute Wqk rows 2b, 2b+1.
// Device barrier (generation-gated, replay-safe), then
// Phase B: QKp = x@Wqk -> A-frags (identical to old qkp_kernel body).
__global__ __launch_bounds__(256) void combo_kernel(const float* __restrict__ x,
                                                    const float* __restrict__ y,
                                                    const float* __restrict__ Wq,
                                                    const float* __restrict__ Wk) {
    __shared__ float wqs[2048];
    const int b = blockIdx.x, t = threadIdx.x;
    const int w = t >> 5, lane = t & 31;

    // ---- phase A1: y fragment packing (one item per thread, split layout)
    {
        int u = b * 256 + t;                     // [0, 32768)
        if (u < 16384) {
            // S B-frag (k8), layout [tile][lane][nt]: key n = tile*32 + nt*8 + g
            int nt = u & 3, ln = (u >> 2) & 31, tile = u >> 7;
            int g = ln >> 2, q = ln & 3;
            int n = tile * 32 + nt * 8 + g;
            float v0 = (2 * q     < 7) ? y[n * 7 + 2 * q]     : 0.f;
            float v1 = (2 * q + 1 < 7) ? y[n * 7 + 2 * q + 1] : 0.f;   // k-dim pad = 0
            g_ySf[u] = packh2(v0, v1);
        } else {
            // PV B-frag (k16), layout [tile][lane][ks][r]: col 7 = 1.0 (Z/Rsum)
            int u2 = u - 16384;
            int r = u2 & 1, ks = (u2 >> 1) & 1, ln = (u2 >> 2) & 31, tile = u2 >> 7;
            int g = ln >> 2, q = ln & 3;
            int k0 = tile * 32 + ks * 16 + r * 8 + 2 * q;
            float v0 = (g < 7) ? y[(size_t)k0 * 7 + g]       : 1.0f;
            float v1 = (g < 7) ? y[(size_t)(k0 + 1) * 7 + g] : 1.0f;
            g_yPf[u2] = packh2(v0, v1);
        }
    }

    // ---- phase A2: Wqk rows 2b (warp 0), 2b+1 (warp 1)
    if (w < 2) {
        int row = b * 2 + w;
        float acc[7] = {};
        #pragma unroll
        for (int i = 0; i < 8; i++) {
            int p = i * 32 + lane;
            float v = Wq[row * 256 + p];
            #pragma unroll
            for (int j = 0; j < 7; j++) acc[j] = fmaf(v, Wk[j * 256 + p], acc[j]);
        }
        #pragma unroll
        for (int j = 0; j < 7; j++) {
            #pragma unroll
            for (int off = 16; off > 0; off >>= 1)
                acc[j] += __shfl_xor_sync(0xffffffffu, acc[j], off);
        }
        if (lane == 0) {
            #pragma unroll
            for (int j = 0; j < 7; j++) g_Wqk[row * 8 + j] = acc[j] * SCALE_L2E;
            g_Wqk[row * 8 + 7] = 0.f;
        }
    }

    // ---- device barrier (generation-gated; replay-safe) ----
    __threadfence();          // phase-A stores visible before arrival
    __syncthreads();          // whole CTA done with phase A
    if (t == 0) {
        unsigned gen = *(volatile unsigned*)&g_gate;   // snapshot BEFORE arriving
        unsigned old = atomicAdd(&g_bar, 1u);
        if (old == 127u) {
            g_bar = 0u;                                // all arrived; reset for replay
            __threadfence();
            atomicAdd(&g_gate, 1u);                    // release (monotonic)
        } else {
            while (*(volatile unsigned*)&g_gate == gen) { }
        }
    }
    __syncthreads();

    // ---- phase B: QKp = x @ Wqk -> A-frags ----
    for (int i = t; i < 2048; i += 256) wqs[i] = g_Wqk[i];
    __syncthreads();

    int u = b * 256 + t;       // 32768 threads
    int ln = u & 31, qg = u >> 5;
    int g = ln >> 2, q = ln & 3;
    int r0 = qg * 16 + g, r1 = r0 + 8;
    int c0 = 2 * q, c1 = c0 + 1;
    float a00 = 0, a01 = 0, a10 = 0, a11 = 0;
    const float4* x0 = (const float4*)(x + (size_t)r0 * 256);
    const float4* x1 = (const float4*)(x + (size_t)r1 * 256);
    #pragma unroll 4
    for (int k4 = 0; k4 < 64; k4++) {
        float4 v0 = x0[k4], v1 = x1[k4];
        const float* ww = &wqs[k4 * 32];
        a00 = fmaf(v0.x, ww[c0], a00);       a01 = fmaf(v0.x, ww[c1], a01);
        a10 = fmaf(v1.x, ww[c0], a10);       a11 = fmaf(v1.x, ww[c1], a11);
        a00 = fmaf(v0.y, ww[8 + c0], a00);   a01 = fmaf(v0.y, ww[8 + c1], a01);
        a10 = fmaf(v1.y, ww[8 + c0], a10);   a11 = fmaf(v1.y, ww[8 + c1], a11);
        a00 = fmaf(v0.z, ww[16 + c0], a00);  a01 = fmaf(v0.z, ww[16 + c1], a01);
        a10 = fmaf(v1.z, ww[16 + c0], a10);  a11 = fmaf(v1.z, ww[16 + c1], a11);
        a00 = fmaf(v0.w, ww[24 + c0], a00);  a01 = fmaf(v0.w, ww[24 + c1], a01);
        a10 = fmaf(v1.w, ww[24 + c0], a10);  a11 = fmaf(v1.w, ww[24 + c1], a11);
    }
    uint2 o;
    o.x = packh2(a00, a01);
    o.y = packh2(a10, a11);
    g_QKf[u] = o;
}

// ---------------------------------------------------------------- fused attention core
// CTA: 256 threads, 128 queries, keys [split*512, +512). smem: 8K + 8K.
#define ATT_SMEM 16384

__global__ __launch_bounds__(256, 4) void attn_kernel() {
    extern __shared__ char smem[];
    const uint32_t sb = smem_u32(smem);
    const uint32_t SY = sb, PVS = sb + 8192;

    const int t = threadIdx.x, w = t >> 5, lane = t & 31;
    const int g = lane >> 2, q = lane & 3;
    const int qblk = blockIdx.x, split = blockIdx.y;

    // load this split's y-fragments (once)
    {
        const uint32_t* ysrc = g_ySf + split * (TILES * 128);
        const uint32_t* psrc = g_yPf + split * (TILES * 128);
        #pragma unroll
        for (int i = 0; i < 2; i++) { int f = t + (i << 8); CP16(SY  + f * 16, ysrc + f * 4); }
        #pragma unroll
        for (int i = 0; i < 2; i++) { int f = t + (i << 8); CP16(PVS + f * 16, psrc + f * 4); }
        CP_COMMIT(); CP_WAIT0();
    }
    __syncthreads();

    uint2 qa = g_QKf[(qblk * 8 + w) * 32 + lane];
    uint32_t a8[2] = { qa.x, qa.y };

    float accE[4] = {}, accR[4] = {};

    #pragma unroll 2
    for (int tile = 0; tile < TILES; tile++) {
        // ---- scores (log2 domain): 16q x 32keys, 4 k8-HMMA, one lds128 ----
        float sc[4][4] = {};
        uint32_t bS[4];
        lds128(bS, SY + (uint32_t)(tile * 128 + lane * 4) * 4);
        mma_f16_k8(sc[0], a8, bS[0]);
        mma_f16_k8(sc[1], a8, bS[1]);
        mma_f16_k8(sc[2], a8, bS[2]);
        mma_f16_k8(sc[3], a8, bS[3]);

        // ---- convert in half2: pack t, E = ex2.f16x2, Rv = max.f16x2 ----
        uint32_t eh[4][2], rh[4][2];
        #pragma unroll
        for (int nt = 0; nt < 4; nt++) {
            uint32_t t01 = packh2(sc[nt][0], sc[nt][1]);
            uint32_t t23 = packh2(sc[nt][2], sc[nt][3]);
            eh[nt][0] = h2ex2(t01);   eh[nt][1] = h2ex2(t23);
            rh[nt][0] = h2relu(t01);  rh[nt][1] = h2relu(t23);
        }

        // ---- PV: accEy += E@[y|1], accRy += R@[y|1]; one lds128, 4 k16-HMMA ----
        uint32_t bP[4];
        lds128(bP, PVS + (uint32_t)(tile * 128 + lane * 4) * 4);
        {
            uint32_t aE0[4] = { eh[0][0], eh[0][1], eh[1][0], eh[1][1] };
            uint32_t aR0[4] = { rh[0][0], rh[0][1], rh[1][0], rh[1][1] };
            mma_f16(accE, aE0, bP[0], bP[1]);
            mma_f16(accR, aR0, bP[0], bP[1]);
        }
        {
            uint32_t aE1[4] = { eh[2][0], eh[2][1], eh[3][0], eh[3][1] };
            uint32_t aR1[4] = { rh[2][0], rh[2][1], rh[3][0], rh[3][1] };
            mma_f16(accE, aE1, bP[2], bP[3]);
            mma_f16(accR, aR1, bP[2], bP[3]);
        }
    }

    // store partials (col 7 carries Z / Rsum')
    const int qrow = qblk * 128 + w * 16 + g;
    const size_t b8 = (size_t)split * (N_Q * 8);
    *(float2*)&g_pE[b8 + (size_t)qrow * 8 + 2 * q]       = make_float2(accE[0], accE[1]);
    *(float2*)&g_pE[b8 + (size_t)(qrow + 8) * 8 + 2 * q] = make_float2(accE[2], accE[3]);
    *(float2*)&g_pR[b8 + (size_t)qrow * 8 + 2 * q]       = make_float2(accR[0], accR[1]);
    *(float2*)&g_pR[b8 + (size_t)(qrow + 8) * 8 + 2 * q] = make_float2(accR[2], accR[3]);
}

// ---------------------------------------------------------------- epilogue: out = c @ Wv
// grid 256 x 256 threads; CTA = 64 query rows (round-13 version).
__global__ __launch_bounds__(256) void epi_kernel(const float* __restrict__ Wv,
                                                  float* __restrict__ out) {
    __shared__ float c_s[64][8];
    const int t = threadIdx.x;
    const int rbase = blockIdx.x * 64;

    // ---- phase 1 ----
    {
        const int row = t >> 2, sp = t & 3;
        const int qr = rbase + row;
        float ea[8] = {}, ra[8] = {};
        #pragma unroll
        for (int i = 0; i < 2; i++) {
            int s = sp * 2 + i;
            const float* pe = &g_pE[(size_t)s * (N_Q * 8) + (size_t)qr * 8];
            const float* pr = &g_pR[(size_t)s * (N_Q * 8) + (size_t)qr * 8];
            float4 e0 = *(const float4*)pe, e1 = *(const float4*)(pe + 4);
            float4 r0 = *(const float4*)pr, r1 = *(const float4*)(pr + 4);
            ea[0] += e0.x; ea[1] += e0.y; ea[2] += e0.z; ea[3] += e0.w;
            ea[4] += e1.x; ea[5] += e1.y; ea[6] += e1.z; ea[7] += e1.w;
            ra[0] += r0.x; ra[1] += r0.y; ra[2] += r0.z; ra[3] += r0.w;
            ra[4] += r1.x; ra[5] += r1.y; ra[6] += r1.z; ra[7] += r1.w;
        }
        #pragma unroll
        for (int j = 0; j < 8; j++) {
            ea[j] += __shfl_xor_sync(0xffffffffu, ea[j], 1);
            ea[j] += __shfl_xor_sync(0xffffffffu, ea[j], 2);
            ra[j] += __shfl_xor_sync(0xffffffffu, ra[j], 1);
            ra[j] += __shfl_xor_sync(0xffffffffu, ra[j], 2);
        }
        if (sp == 0) {
            float iz = 1.f / ea[7];
            float dn = 1.f / fmaf(C01LN2, ra[7], 1.f);
            #pragma unroll
            for (int d = 0; d < 7; d++)
                c_s[row][d] = fmaf(ea[d], iz, C01LN2 * ra[d]) * dn;
            c_s[row][7] = 0.f;
        }
    }
    __syncthreads();

    // ---- phase 2: thread t -> float4-col j = t&63, rows rg*16..+16 ----
    const int j  = t & 63;
    const int rg = t >> 6;
    float4 wv4[7];
    #pragma unroll
    for (int d = 0; d < 7; d++)
        wv4[d] = ((const float4*)(Wv + (size_t)d * 256))[j];

    #pragma unroll 4
    for (int r = 0; r < 16; r++) {
        int row = rg * 16 + r;
        const float* c = c_s[row];
        float4 o;
        o.x = c[0] * wv4[0].x; o.y = c[0] * wv4[0].y;
        o.z = c[0] * wv4[0].z; o.w = c[0] * wv4[0].w;
        #pragma unroll
        for (int d = 1; d < 7; d++) {
            o.x = fmaf(c[d], wv4[d].x, o.x);
            o.y = fmaf(c[d], wv4[d].y, o.y);
            o.z = fmaf(c[d], wv4[d].z, o.z);
            o.w = fmaf(c[d], wv4[d].w, o.w);
        }
        ((float4*)(out + (size_t)(rbase + row) * 256))[j] = o;
    }
}

// ---------------------------------------------------------------------------
extern "C" void kernel_launch(void* const* d_in, const int* in_sizes, int n_in,
                              void* d_out, int out_size) {
    const float* x  = (const float*)d_in[0];
    const float* y  = (const float*)d_in[1];
    const float* Wq = (const float*)d_in[2];
    const float* Wk = (const float*)d_in[3];
    const float* Wv = (const float*)d_in[4];
    float* out = (float*)d_out;

    cudaFuncSetAttribute(attn_kernel, cudaFuncAttributeMaxDynamicSharedMemorySize,
                         ATT_SMEM);

    combo_kernel<<<128, 256>>>(x, y, Wq, Wk);
    attn_kernel <<<dim3(N_Q / 128, KSPLIT), 256, ATT_SMEM>>>();
    epi_kernel  <<<256, 256>>>(Wv, out);
}